// round 13
// baseline (speedup 1.0000x reference)
#include <cuda_runtime.h>

#define BATCH 8
#define DIM 256
#define SEQ 16384
#define KK 3
#define HID 85
#define OUTC (DIM*KK)
#define BN_EPS 1e-5f
#define FULLM 0xffffffffu

// Scratch (device globals — no allocation allowed)
__device__ float g_pooled[BATCH * DIM];
__device__ float g_w[BATCH * OUTC];

// ---------------------------------------------------------------------------
// Kernel 1: mean over seq for each (b, c) row. grid=(DIM, BATCH), block=512.
// 8 front-batched float4 loads per thread (proven 5.8-5.9 TB/s config).
// Triggers the dependent launch EARLY (right after its loads are consumed)
// so mlp/conv prologues overlap the remaining ~20us of pool execution.
// ---------------------------------------------------------------------------
__global__ void pool_kernel(const float* __restrict__ x) {
    const int c = blockIdx.x;
    const int b = blockIdx.y;
    const size_t rowoff = ((size_t)b * DIM + c) * SEQ;
    const float4* row = (const float4*)(x + rowoff);

    float4 v[8];
    #pragma unroll
    for (int j = 0; j < 8; j++)
        v[j] = row[threadIdx.x + j * 512];

    float s = 0.f;
    #pragma unroll
    for (int j = 0; j < 8; j++)
        s += (v[j].x + v[j].y) + (v[j].z + v[j].w);

    // All loads issued & consumed -> let the successor start launching.
    cudaTriggerProgrammaticLaunchCompletion();

    #pragma unroll
    for (int off = 16; off > 0; off >>= 1)
        s += __shfl_down_sync(FULLM, s, off);

    __shared__ float sm[16];
    if ((threadIdx.x & 31) == 0) sm[threadIdx.x >> 5] = s;
    __syncthreads();
    if (threadIdx.x < 16) {
        float t = sm[threadIdx.x];
        #pragma unroll
        for (int off = 8; off > 0; off >>= 1)
            t += __shfl_down_sync(0xffffu, t, off);
        if (threadIdx.x == 0) g_pooled[b * DIM + c] = t * (1.f / SEQ);
    }
}

// ---------------------------------------------------------------------------
// Kernel 2: tiny MLP. grid=(4, BATCH), block=256. PDL secondary:
// triggers at entry (so conv can ramp through the mlp bubble), prefetches
// w1/w2 into L2 pre-sync, then gridsyncs and computes.
// ---------------------------------------------------------------------------
__global__ void mlp_kernel(const float* __restrict__ w1,
                           const float* __restrict__ gamma,
                           const float* __restrict__ beta,
                           const float* __restrict__ mean,
                           const float* __restrict__ var,
                           const float* __restrict__ w2,
                           const float* __restrict__ b2) {
    cudaTriggerProgrammaticLaunchCompletion();

    const int b = blockIdx.y;
    const int chunk = blockIdx.x;          // 0..3, 192 outputs each
    const int tid = threadIdx.x;
    const int gthr = (b * 4 + chunk) * 256 + tid;   // 0..8191

    // ---- pre-sync: prefetch weights into L2 (independent of pool) ----
    {
        const float4* w1f4 = (const float4*)w1;     // 5440 f4
        const float4* w2f4 = (const float4*)w2;     // 16320 f4
        if (gthr < 5440) {
            float4 p = __ldcg(w1f4 + gthr);
            asm volatile("" :: "f"(p.x), "f"(p.y), "f"(p.z), "f"(p.w));
        }
        #pragma unroll
        for (int r = 0; r < 2; r++) {
            int i = r * 8192 + gthr;
            if (i < 16320) {
                float4 p = __ldcg(w2f4 + i);
                asm volatile("" :: "f"(p.x), "f"(p.y), "f"(p.z), "f"(p.w));
            }
        }
    }

    cudaGridDependencySynchronize();       // pool's g_pooled now visible

    __shared__ float ps[DIM];
    __shared__ float ys[HID];

    ps[tid] = g_pooled[b * DIM + tid];
    __syncthreads();

    if (tid < HID) {
        const float* wr = w1 + tid * DIM;
        float acc = 0.f;
        #pragma unroll 8
        for (int c = 0; c < DIM; c++) acc = fmaf(wr[c], ps[c], acc);
        float v = (acc - mean[tid]) * (gamma[tid] * rsqrtf(var[tid] + BN_EPS)) + beta[tid];
        ys[tid] = fmaxf(v, 0.f);
    }
    __syncthreads();

    const int o = chunk * 192 + tid;
    if (tid < 192) {
        const float* wr = w2 + o * HID;
        float acc = b2[o];
        #pragma unroll 5
        for (int h = 0; h < HID; h++) acc = fmaf(wr[h], ys[h], acc);
        g_w[b * OUTC + o] = acc;
    }
}

// ---------------------------------------------------------------------------
// Kernel 3: depthwise 3-tap conv. PDL secondary: x loads + halo exchange
// BEFORE gridsync (overlapping pool/mlp execution); g_w read + fma + stores
// after. grid=(8, DIM, BATCH), block=256, 2 float4/thread, __stcs stores.
// ---------------------------------------------------------------------------
__global__ void conv_kernel(const float* __restrict__ x,
                            const float* __restrict__ bias,
                            float* __restrict__ out) {
    const int b = (BATCH - 1) - blockIdx.z;
    const int c = (DIM - 1) - blockIdx.y;
    const int chunk = (int)(gridDim.x - 1) - blockIdx.x;     // 0..7
    const int tid = threadIdx.x;
    const int lane = tid & 31;
    const size_t rowoff = ((size_t)b * DIM + c) * SEQ;

    const int p0 = chunk * 256 + tid;          // float4 idx, first half
    const int p1 = p0 + 2048;                  // second half
    const int t0 = p0 * 4;
    const int t1 = p1 * 4;

    // ---- pre-sync: the entire x read for this thread ----
    const float4 xa = *(const float4*)(x + rowoff + t0);
    const float4 xb = *(const float4*)(x + rowoff + t1);
    const float bb = __ldg(bias + c);

    float xla = __shfl_up_sync(FULLM, xa.w, 1);
    float xra = __shfl_down_sync(FULLM, xa.x, 1);
    float xlb = __shfl_up_sync(FULLM, xb.w, 1);
    float xrb = __shfl_down_sync(FULLM, xb.x, 1);

    if (lane == 0) {
        xla = (t0 == 0) ? 0.f : __ldg(x + rowoff + t0 - 1);
        xlb = __ldg(x + rowoff + t1 - 1);
    }
    if (lane == 31) {
        xra = __ldg(x + rowoff + t0 + 4);
        xrb = (t1 + 4 >= SEQ) ? 0.f : __ldg(x + rowoff + t1 + 4);
    }

    cudaGridDependencySynchronize();           // mlp's g_w now visible

    const float w0  = g_w[b * OUTC + c * KK + 0];
    const float w1v = g_w[b * OUTC + c * KK + 1];
    const float w2v = g_w[b * OUTC + c * KK + 2];

    float4 oa, ob;
    oa.x = fmaf(w0, xla,  fmaf(w1v, xa.x, fmaf(w2v, xa.y, bb)));
    oa.y = fmaf(w0, xa.x, fmaf(w1v, xa.y, fmaf(w2v, xa.z, bb)));
    oa.z = fmaf(w0, xa.y, fmaf(w1v, xa.z, fmaf(w2v, xa.w, bb)));
    oa.w = fmaf(w0, xa.z, fmaf(w1v, xa.w, fmaf(w2v, xra,  bb)));

    ob.x = fmaf(w0, xlb,  fmaf(w1v, xb.x, fmaf(w2v, xb.y, bb)));
    ob.y = fmaf(w0, xb.x, fmaf(w1v, xb.y, fmaf(w2v, xb.z, bb)));
    ob.z = fmaf(w0, xb.y, fmaf(w1v, xb.z, fmaf(w2v, xb.w, bb)));
    ob.w = fmaf(w0, xb.z, fmaf(w1v, xb.w, fmaf(w2v, xrb,  bb)));

    __stcs((float4*)(out + rowoff + t0), oa);
    __stcs((float4*)(out + rowoff + t1), ob);
}

// ---------------------------------------------------------------------------
// Launch: pool normally; mlp and conv as PDL secondaries. Primaries trigger
// early so secondary prologues overlap predecessor execution.
// Inputs: x, w1, bn_gamma, bn_beta, bn_mean, bn_var, w2, b2, bias.
// ---------------------------------------------------------------------------
extern "C" void kernel_launch(void* const* d_in, const int* in_sizes, int n_in,
                              void* d_out, int out_size) {
    const float* x     = (const float*)d_in[0];
    const float* w1    = (const float*)d_in[1];
    const float* gamma = (const float*)d_in[2];
    const float* beta  = (const float*)d_in[3];
    const float* mean  = (const float*)d_in[4];
    const float* var   = (const float*)d_in[5];
    const float* w2    = (const float*)d_in[6];
    const float* b2    = (const float*)d_in[7];
    const float* bias  = (const float*)d_in[8];
    float* out = (float*)d_out;

    dim3 pg(DIM, BATCH);
    pool_kernel<<<pg, 512>>>(x);

    cudaLaunchAttribute attr[1];
    attr[0].id = cudaLaunchAttributeProgrammaticStreamSerialization;
    attr[0].val.programmaticStreamSerializationAllowed = 1;

    {
        cudaLaunchConfig_t cfg = {};
        cfg.gridDim = dim3(4, BATCH);
        cfg.blockDim = dim3(256);
        cfg.attrs = attr;
        cfg.numAttrs = 1;
        cudaLaunchKernelEx(&cfg, mlp_kernel, w1, gamma, beta, mean, var, w2, b2);
    }
    {
        cudaLaunchConfig_t cfg = {};
        cfg.gridDim = dim3(8, DIM, BATCH);
        cfg.blockDim = dim3(256);
        cfg.attrs = attr;
        cfg.numAttrs = 1;
        cudaLaunchKernelEx(&cfg, conv_kernel, x, bias, out);
    }
}